// round 8
// baseline (speedup 1.0000x reference)
#include <cuda_runtime.h>
#include <cstdint>

// RSNALoss fused, flat-chunk version:
//  Grid = (32 chunks) x (128 batches) = 4096 blocks; each block owns ONE 256-row
//  chunk of one batch: cp.async the 20 KB chunk (perfectly coalesced 16B copies),
//  consume one row/thread from SMEM, tree-reduce 20 accumulators, write partials.
//  Parallelism comes from 8 resident blocks/SM (64 warps), not intra-block
//  pipelining -> no latency bubbles, fine-grained load balance over variable
//  seq_lens.
//  Last block (atomic ticket) finalizes: 256 threads = (batch, acc-half) pairs
//  sum the 32 chunk-partials each, exchange via SMEM, thread b computes batch b's
//  loss terms, block-reduce to the scalar. Deterministic (ticket only selects the
//  finalizer; the summed array is complete and fixed).

#define BATCH 128
#define SEQ   8192
#define NT    256
#define CHUNK 256
#define CPB   (SEQ / CHUNK)          // 32 chunks per batch
#define NBLK  (BATCH * CPB)          // 4096 blocks
#define CH10  (CHUNK * 10)           // 2560 floats per tensor per chunk
#define F4PT  (CH10 / 4)             // 640 float4 per tensor per chunk
#define NACC  20
#define NWARP (NT / 32)

#define IMAGE_WEIGHT 0.0736196319f

__constant__ float c_w[9] = {
    0.0736196319f, 0.09202453988f, 0.1042944785f, 0.1042944785f,
    0.1877300613f, 0.06257668712f, 0.06257668712f, 0.2346625767f,
    0.0782208589f
};

__device__ __align__(16) float g_partials[NACC * NBLK];  // [acc][b*CPB + chunk]
__device__ unsigned int g_ticket;                        // zero-init; reset by last block

__device__ __forceinline__ void cp16(uint32_t s, const void* g, bool p)
{
    asm volatile(
        "{ .reg .pred q; setp.ne.u32 q, %2, 0;"
        "  @q cp.async.cg.shared.global [%0], [%1], 16; }"
        :: "r"(s), "l"(g), "r"((int)p));
}

__global__ __launch_bounds__(NT)
void rsna_fused_kernel(const float* __restrict__ pred,
                       const float* __restrict__ label,
                       const int*   __restrict__ seq_lens,
                       float* __restrict__ out)
{
    const int b   = blockIdx.y;
    const int ch  = blockIdx.x;
    const int tid = threadIdx.x;
    const int sl  = __ldg(&seq_lens[b]);
    const int base = ch * CHUNK;

    __shared__ __align__(16) float s_pred[CH10];
    __shared__ __align__(16) float s_lab [CH10];

    float acc[NACC];
#pragma unroll
    for (int i = 0; i < NACC; i++) acc[i] = 0.0f;

    const bool active = (base < sl);

    if (active) {
        // ---- fetch: 1280 coalesced 16B cp.async over 256 threads (5 each) ----
        const int lim = (sl - base) * 10;    // valid floats in this chunk
        const float4* pg = (const float4*)(pred  + ((size_t)b * SEQ + base) * 10);
        const float4* lg = (const float4*)(label + ((size_t)b * SEQ + base) * 10);
        const uint32_t sp = (uint32_t)__cvta_generic_to_shared(s_pred);
        const uint32_t sy = (uint32_t)__cvta_generic_to_shared(s_lab);
#pragma unroll
        for (int j = 0; j < 5; j++) {
            const int idx = tid + j * NT;
            if (idx < F4PT) {
                cp16(sp + idx * 16, pg + idx, (idx * 4) < lim);
            } else {
                const int i2 = idx - F4PT;
                cp16(sy + i2 * 16, lg + i2, (i2 * 4) < lim);
            }
        }
        asm volatile("cp.async.commit_group;");
        asm volatile("cp.async.wait_group 0;");
        __syncthreads();

        // ---- consume: one row per thread from SMEM ----
        if (base + tid < sl) {
            const float2* pr = (const float2*)&s_pred[tid * 10];
            const float2* lr = (const float2*)&s_lab [tid * 10];
            float2 p0 = pr[0], p1 = pr[1], p2 = pr[2], p3 = pr[3], p4 = pr[4];
            float2 l0 = lr[0], l1 = lr[1], l2 = lr[2], l3 = lr[3], l4 = lr[4];

            acc[0] += p0.y; acc[1] += p1.x; acc[2] += p1.y; acc[3] += p2.x;
            acc[4] += p2.y; acc[5] += p3.x; acc[6] += p3.y; acc[7] += p4.x;
            acc[8] += p4.y;

            acc[9]  += l0.y; acc[10] += l1.x; acc[11] += l1.y; acc[12] += l2.x;
            acc[13] += l2.y; acc[14] += l3.x; acc[15] += l3.y; acc[16] += l4.x;
            acc[17] += l4.y;

            const float p0v = p0.x, y0v = l0.x;
            acc[18] += y0v;
            acc[19] += -(y0v * __logf(p0v) + (1.0f - y0v) * __logf(1.0f - p0v));
        }
    }

    // ---- warp + block reduce the 20 accumulators ----
#pragma unroll
    for (int i = 0; i < NACC; i++) {
#pragma unroll
        for (int off = 16; off > 0; off >>= 1)
            acc[i] += __shfl_xor_sync(0xFFFFFFFFu, acc[i], off);
    }

    __shared__ float s_red[NWARP * NACC];
    const int wid  = tid >> 5;
    const int lane = tid & 31;
    if (lane == 0) {
#pragma unroll
        for (int i = 0; i < NACC; i++) s_red[wid * NACC + i] = acc[i];
    }
    __syncthreads();

    if (tid < NACC) {
        float s = 0.0f;
#pragma unroll
        for (int w = 0; w < NWARP; w++) s += s_red[w * NACC + tid];
        g_partials[tid * NBLK + b * CPB + ch] = s;   // accumulator-major
    }

    // ---- ticket: last finished block finalizes ----
    __shared__ int s_last;
    __threadfence();
    __syncthreads();
    if (tid == 0) {
        unsigned int t = atomicAdd(&g_ticket, 1u);
        s_last = (t == (unsigned int)(NBLK - 1)) ? 1 : 0;
    }
    __syncthreads();
    if (!s_last) return;

    if (tid == 0) g_ticket = 0;
    __threadfence();

    // ---- Phase 2: 256 threads = (batch, acc-half); each sums 32 chunk-partials
    //      for 10 accumulators, exchanges via SMEM; thread b finalizes batch b.
    {
        const int fb = tid >> 1;          // batch 0..127
        const int gh = tid & 1;           // acc half: 0 -> accs 0..9, 1 -> 10..19
        __shared__ float s_fin[BATCH][NACC];

        const float4* gp = (const float4*)g_partials;
#pragma unroll
        for (int i = 0; i < 10; i++) {
            const int a = gh * 10 + i;
            const float4* p4 = gp + a * (NBLK / 4) + fb * (CPB / 4);  // 8 float4
            float s = 0.0f;
#pragma unroll
            for (int j = 0; j < CPB / 4; j++) {
                float4 v = p4[j];
                s += ((v.x + v.y) + (v.z + v.w));
            }
            s_fin[fb][a] = s;
        }
        __syncthreads();

        float num = 0.0f, wsum = 0.0f;
        if (tid < BATCH) {
            float a[NACC];
#pragma unroll
            for (int i = 0; i < NACC; i++) a[i] = s_fin[tid][i];

            const float len = (float)__ldg(&seq_lens[tid]);
            const float inv = 1.0f / len;

            float exam = 0.0f;
#pragma unroll
            for (int c = 0; c < 9; c++) {
                const float pm = a[c]     * inv;
                const float ym = a[9 + c] * inv;
                exam += c_w[c] * (-(ym * __logf(pm) + (1.0f - ym) * __logf(1.0f - pm)));
            }

            const float y0m = a[18] * inv;
            const float iw  = IMAGE_WEIGHT * y0m;
            num  = exam + a[19] * iw;
            wsum = iw * len;
        }

#pragma unroll
        for (int off = 16; off > 0; off >>= 1) {
            num  += __shfl_xor_sync(0xFFFFFFFFu, num,  off);
            wsum += __shfl_xor_sync(0xFFFFFFFFu, wsum, off);
        }
        __shared__ float s_num[NWARP], s_ws[NWARP];
        if (lane == 0) { s_num[wid] = num; s_ws[wid] = wsum; }
        __syncthreads();
        if (tid == 0) {
            float n = 0.0f, w = 0.0f;
#pragma unroll
            for (int i = 0; i < NWARP; i++) { n += s_num[i]; w += s_ws[i]; }
            float sumw = 0.0f;
#pragma unroll
            for (int c = 0; c < 9; c++) sumw += c_w[c];
            out[0] = n / ((float)BATCH * sumw + w);
        }
    }
}

extern "C" void kernel_launch(void* const* d_in, const int* in_sizes, int n_in,
                              void* d_out, int out_size)
{
    const float* pred  = (const float*)d_in[0];
    const float* label = (const float*)d_in[1];
    const int*   slens = (const int*)d_in[2];
    float* out = (float*)d_out;

    dim3 grid(CPB, BATCH);
    rsna_fused_kernel<<<grid, NT>>>(pred, label, slens, out);
}

// round 9
// speedup vs baseline: 2.5653x; 2.5653x over previous
#include <cuda_runtime.h>
#include <cstdint>

// RSNALoss fused, smem-staged, small-block/high-stream-count version:
//  Each block (128 threads) owns a 1024-row tile of one batch, processed as
//  8 chunks of 128 rows, double-buffered cp.async (coalesced 16B copies).
//  20KB smem/block -> ~10 resident blocks/SM = 2x the concurrent fetch streams
//  of the 256-thread variant, with the same per-thread amortization (8 rows).
//  Last block (atomic ticket) finalizes. Deterministic: ticket only selects the
//  finalizing block; the partial array it reads is complete and fixed.

#define BATCH 128
#define SEQ   8192
#define NT    128
#define CHUNK 128                       // rows per chunk (== NT)
#define CH10  (CHUNK * 10)              // 1280 floats per tensor per chunk
#define F4PT  (CH10 / 4)                // 320 float4 per tensor per chunk
#define TILE_CHUNKS 8
#define TILE_ROWS   (CHUNK * TILE_CHUNKS)   // 1024
#define BPB   (SEQ / TILE_ROWS)         // 8 tiles per batch
#define NBLK  (BATCH * BPB)             // 1024 blocks
#define NACC  20
#define NWARP (NT / 32)

#define IMAGE_WEIGHT 0.0736196319f

__constant__ float c_w[9] = {
    0.0736196319f, 0.09202453988f, 0.1042944785f, 0.1042944785f,
    0.1877300613f, 0.06257668712f, 0.06257668712f, 0.2346625767f,
    0.0782208589f
};

__device__ __align__(16) float g_partials[NACC * NBLK];  // [acc][b*BPB + tile]
__device__ unsigned int g_ticket;                        // zero-init; reset by last block

__device__ __forceinline__ void cp16(uint32_t s, const void* g, bool p)
{
    asm volatile(
        "{ .reg .pred q; setp.ne.u32 q, %2, 0;"
        "  @q cp.async.cg.shared.global [%0], [%1], 16; }"
        :: "r"(s), "l"(g), "r"((int)p));
}

__global__ __launch_bounds__(NT, 10)
void rsna_fused_kernel(const float* __restrict__ pred,
                       const float* __restrict__ label,
                       const int*   __restrict__ seq_lens,
                       float* __restrict__ out)
{
    const int b    = blockIdx.y;
    const int tile = blockIdx.x;
    const int tid  = threadIdx.x;
    const int sl   = __ldg(&seq_lens[b]);

    __shared__ __align__(16) float s_pred[2][CH10];
    __shared__ __align__(16) float s_lab [2][CH10];

    float acc[NACC];
#pragma unroll
    for (int i = 0; i < NACC; i++) acc[i] = 0.0f;

    const int tile_base = tile * TILE_ROWS;
    int nch = 0;
    {
        const int rem = sl - tile_base;
        if (rem > 0) nch = min(TILE_CHUNKS, (rem + CHUNK - 1) / CHUNK);
    }

    const float* pbase = pred  + (size_t)b * SEQ * 10;
    const float* lbase = label + (size_t)b * SEQ * 10;

    auto prefetch = [&](int c, int buf) {
        const int cb  = tile_base + c * CHUNK;
        const int lim = (sl - cb) * 10;     // valid floats in this chunk
        const float4* pg = (const float4*)(pbase + (size_t)cb * 10);
        const float4* lg = (const float4*)(lbase + (size_t)cb * 10);
        const uint32_t sp = (uint32_t)__cvta_generic_to_shared(&s_pred[buf][0]);
        const uint32_t sy = (uint32_t)__cvta_generic_to_shared(&s_lab [buf][0]);
#pragma unroll
        for (int j = 0; j < 5; j++) {       // 640 float4 over 128 threads
            const int idx = tid + j * NT;
            if (idx < F4PT) {
                cp16(sp + idx * 16, pg + idx, (idx * 4) < lim);
            } else {
                const int i2 = idx - F4PT;
                cp16(sy + i2 * 16, lg + i2, (i2 * 4) < lim);
            }
        }
        asm volatile("cp.async.commit_group;");
    };

    if (nch > 0) prefetch(0, 0);

    for (int c = 0; c < nch; c++) {
        if (c + 1 < nch) {
            prefetch(c + 1, (c + 1) & 1);
            asm volatile("cp.async.wait_group 1;");
        } else {
            asm volatile("cp.async.wait_group 0;");
        }
        __syncthreads();

        const int row = tile_base + c * CHUNK + tid;
        if (row < sl) {
            const float2* pr = (const float2*)&s_pred[c & 1][tid * 10];
            const float2* lr = (const float2*)&s_lab [c & 1][tid * 10];
            float2 p0 = pr[0], p1 = pr[1], p2 = pr[2], p3 = pr[3], p4 = pr[4];
            float2 l0 = lr[0], l1 = lr[1], l2 = lr[2], l3 = lr[3], l4 = lr[4];

            acc[0] += p0.y; acc[1] += p1.x; acc[2] += p1.y; acc[3] += p2.x;
            acc[4] += p2.y; acc[5] += p3.x; acc[6] += p3.y; acc[7] += p4.x;
            acc[8] += p4.y;

            acc[9]  += l0.y; acc[10] += l1.x; acc[11] += l1.y; acc[12] += l2.x;
            acc[13] += l2.y; acc[14] += l3.x; acc[15] += l3.y; acc[16] += l4.x;
            acc[17] += l4.y;

            const float p0v = p0.x, y0v = l0.x;
            acc[18] += y0v;
            acc[19] += -(y0v * __logf(p0v) + (1.0f - y0v) * __logf(1.0f - p0v));
        }
        __syncthreads();   // buffer (c&1) is rewritten by prefetch(c+2)
    }

    // ---- warp + block reduce the 20 accumulators (amortized over 8 rows) ----
#pragma unroll
    for (int i = 0; i < NACC; i++) {
#pragma unroll
        for (int off = 16; off > 0; off >>= 1)
            acc[i] += __shfl_xor_sync(0xFFFFFFFFu, acc[i], off);
    }

    __shared__ float s_red[NWARP * NACC];
    const int wid  = tid >> 5;
    const int lane = tid & 31;
    if (lane == 0) {
#pragma unroll
        for (int i = 0; i < NACC; i++) s_red[wid * NACC + i] = acc[i];
    }
    __syncthreads();

    if (tid < NACC) {
        float s = 0.0f;
#pragma unroll
        for (int w = 0; w < NWARP; w++) s += s_red[w * NACC + tid];
        g_partials[tid * NBLK + b * BPB + tile] = s;   // accumulator-major
    }

    // ---- ticket: last finished block finalizes ----
    __shared__ int s_last;
    __threadfence();
    __syncthreads();
    if (tid == 0) {
        unsigned int t = atomicAdd(&g_ticket, 1u);
        s_last = (t == (unsigned int)(NBLK - 1)) ? 1 : 0;
    }
    __syncthreads();
    if (!s_last) return;

    if (tid == 0) g_ticket = 0;
    __threadfence();

    // ---- Phase 2: thread b (<128) finalizes batch b; L2-hot coalesced float4 ----
    float num = 0.0f, wsum = 0.0f;
    if (tid < BATCH) {
        const float4* gp = (const float4*)g_partials;
        float a[NACC];
#pragma unroll
        for (int i = 0; i < NACC; i++) {
            float4 x = gp[i * (NBLK / 4) + tid * 2];
            float4 y = gp[i * (NBLK / 4) + tid * 2 + 1];
            a[i] = ((x.x + x.y) + (x.z + x.w)) + ((y.x + y.y) + (y.z + y.w));
        }

        const float len = (float)__ldg(&seq_lens[tid]);
        const float inv = 1.0f / len;

        float exam = 0.0f;
#pragma unroll
        for (int c = 0; c < 9; c++) {
            const float pm = a[c]     * inv;
            const float ym = a[9 + c] * inv;
            exam += c_w[c] * (-(ym * __logf(pm) + (1.0f - ym) * __logf(1.0f - pm)));
        }

        const float y0m = a[18] * inv;
        const float iw  = IMAGE_WEIGHT * y0m;
        num  = exam + a[19] * iw;
        wsum = iw * len;
    }

#pragma unroll
    for (int off = 16; off > 0; off >>= 1) {
        num  += __shfl_xor_sync(0xFFFFFFFFu, num,  off);
        wsum += __shfl_xor_sync(0xFFFFFFFFu, wsum, off);
    }
    __shared__ float s_num[NWARP], s_ws[NWARP];
    if (lane == 0) { s_num[wid] = num; s_ws[wid] = wsum; }
    __syncthreads();
    if (tid == 0) {
        float n = 0.0f, w = 0.0f;
#pragma unroll
        for (int i = 0; i < NWARP; i++) { n += s_num[i]; w += s_ws[i]; }
        float sumw = 0.0f;
#pragma unroll
        for (int c = 0; c < 9; c++) sumw += c_w[c];
        out[0] = n / ((float)BATCH * sumw + w);
    }
}

extern "C" void kernel_launch(void* const* d_in, const int* in_sizes, int n_in,
                              void* d_out, int out_size)
{
    const float* pred  = (const float*)d_in[0];
    const float* label = (const float*)d_in[1];
    const int*   slens = (const int*)d_in[2];
    float* out = (float*)d_out;

    dim3 grid(BPB, BATCH);
    rsna_fused_kernel<<<grid, NT>>>(pred, label, slens, out);
}